// round 1
// baseline (speedup 1.0000x reference)
#include <cuda_runtime.h>

#define B_   16
#define S_   1024
#define DM_  768
#define H_   12
#define DH_  64
#define MTOT (B_ * S_)   // 16384

// Scratch (allocation-free rule: __device__ globals)
__device__ float g_q[(size_t)B_ * H_ * S_ * DH_];
__device__ float g_k[(size_t)B_ * H_ * S_ * DH_];
__device__ float g_v[(size_t)B_ * H_ * S_ * DH_];
__device__ float g_ctx[(size_t)B_ * S_ * DM_];

// ---------------- GEMM core: Y[m,n] = sum_k A[m,k] * W[n,k] ----------------
// Block tile 64x64, BK=16, 256 threads (16x16), 4x4 per-thread microtile.
#define BM 64
#define BN 64
#define BK 16
#define ASTRIDE 68   // padded k-major stride (conflict spreading, 16B aligned rows)

__device__ __forceinline__ void gemm_core(const float* __restrict__ A,
                                          const float* __restrict__ W,
                                          float* Asm, float* Bsm,
                                          int m0, int n0, float acc[4][4])
{
    const int tid = threadIdx.x;
    const int ty  = tid >> 4;        // 0..15 (m microtile)
    const int tx  = tid & 15;        // 0..15 (n microtile)
    const int lr  = tid >> 2;        // 0..63 (load row)
    const int lk  = (tid & 3) << 2;  // 0,4,8,12 (load k base)

    for (int kt = 0; kt < DM_; kt += BK) {
        float4 av = *(const float4*)(A + (m0 + lr) * DM_ + kt + lk);
        float4 wv = *(const float4*)(W + (n0 + lr) * DM_ + kt + lk);
        __syncthreads();   // previous compute done before smem overwrite
        Asm[(lk + 0) * ASTRIDE + lr] = av.x;
        Asm[(lk + 1) * ASTRIDE + lr] = av.y;
        Asm[(lk + 2) * ASTRIDE + lr] = av.z;
        Asm[(lk + 3) * ASTRIDE + lr] = av.w;
        Bsm[(lk + 0) * ASTRIDE + lr] = wv.x;
        Bsm[(lk + 1) * ASTRIDE + lr] = wv.y;
        Bsm[(lk + 2) * ASTRIDE + lr] = wv.z;
        Bsm[(lk + 3) * ASTRIDE + lr] = wv.w;
        __syncthreads();
#pragma unroll
        for (int k = 0; k < BK; k++) {
            float4 a = *(const float4*)(Asm + k * ASTRIDE + ty * 4);
            float4 b = *(const float4*)(Bsm + k * ASTRIDE + tx * 4);
            float am[4] = {a.x, a.y, a.z, a.w};
            float bn[4] = {b.x, b.y, b.z, b.w};
#pragma unroll
            for (int i = 0; i < 4; i++)
#pragma unroll
                for (int j = 0; j < 4; j++)
                    acc[i][j] = fmaf(am[i], bn[j], acc[i][j]);
        }
    }
}

// ---------------- Kernel 1: fused QKV projection ----------------
// grid = (MTOT/64, DM/64 = 12, 3); BN==DH so blockIdx.y == head index.
// Output layout [B, H, S, Dh] for the attention kernel.
__global__ void __launch_bounds__(256) qkv_kernel(
    const float* __restrict__ x,
    const float* __restrict__ Wq, const float* __restrict__ bq,
    const float* __restrict__ Wk, const float* __restrict__ bk,
    const float* __restrict__ Wv, const float* __restrict__ bv)
{
    __shared__ __align__(16) float Asm[BK * ASTRIDE];
    __shared__ __align__(16) float Bsm[BK * ASTRIDE];

    const int which = blockIdx.z;
    const float* W    = (which == 0) ? Wq : (which == 1) ? Wk : Wv;
    const float* bias = (which == 0) ? bq : (which == 1) ? bk : bv;
    float* out        = (which == 0) ? g_q : (which == 1) ? g_k : g_v;

    const int m0 = blockIdx.x * BM;
    const int n0 = blockIdx.y * BN;
    float acc[4][4] = {};
    gemm_core(x, W, Asm, Bsm, m0, n0, acc);

    const int ty = threadIdx.x >> 4, tx = threadIdx.x & 15;
    const int h  = blockIdx.y;       // BN == DH == 64
    float4 bb = *(const float4*)(bias + n0 + tx * 4);
#pragma unroll
    for (int i = 0; i < 4; i++) {
        int m = m0 + ty * 4 + i;
        int b = m >> 10, s = m & 1023;
        float4 o = make_float4(acc[i][0] + bb.x, acc[i][1] + bb.y,
                               acc[i][2] + bb.z, acc[i][3] + bb.w);
        *(float4*)(out + (((b * H_ + h) * S_ + s) * DH_ + tx * 4)) = o;
    }
}

// ---------------- Kernel 2: flash attention (fp32) ----------------
// grid = (S/64, H, B), 256 threads. 64-query tile, streams K/V in 64-row tiles.
// Smem: Qt (d-major Q), KP (d-major K, reused as q-major P^T), Vs. 48KB exactly.
__global__ void __launch_bounds__(256) attn_kernel()
{
    __shared__ __align__(16) float Qt[64 * 64];  // Qt[d*64 + q]
    __shared__ __align__(16) float KP[64 * 64];  // Kt[d*64 + k]  /  Pt[k*64 + q]
    __shared__ __align__(16) float Vs[64 * 64];  // Vs[k*64 + d]

    const int tid  = threadIdx.x;
    const int ty   = tid >> 4, tx = tid & 15;
    const int q0   = blockIdx.x * 64;
    const int head = blockIdx.y, batch = blockIdx.z;
    const int base = ((batch * H_ + head) * S_) * DH_;
    const float* qb = g_q + base;
    const float* kb = g_k + base;
    const float* vb = g_v + base;

    const int lr16 = tid >> 4;        // 0..15
    const int lc4  = (tid & 15) * 4;  // 0..60

    // Load Q tile transposed to d-major
#pragma unroll
    for (int r = 0; r < 4; r++) {
        int row = lr16 + r * 16;
        float4 v = *(const float4*)(qb + (q0 + row) * DH_ + lc4);
        Qt[(lc4 + 0) * 64 + row] = v.x;
        Qt[(lc4 + 1) * 64 + row] = v.y;
        Qt[(lc4 + 2) * 64 + row] = v.z;
        Qt[(lc4 + 3) * 64 + row] = v.w;
    }

    float mi[4], li[4], accO[4][4];
#pragma unroll
    for (int i = 0; i < 4; i++) {
        mi[i] = -1e30f; li[i] = 0.f;
#pragma unroll
        for (int j = 0; j < 4; j++) accO[i][j] = 0.f;
    }

    for (int t = 0; t < S_ / 64; t++) {
        const float* ktile = kb + t * 64 * DH_;
        const float* vtile = vb + t * 64 * DH_;
        __syncthreads();  // prior PV reads of KP/Vs complete (also orders Qt@t=0)
#pragma unroll
        for (int r = 0; r < 4; r++) {
            int row = lr16 + r * 16;
            float4 kv = *(const float4*)(ktile + row * DH_ + lc4);
            KP[(lc4 + 0) * 64 + row] = kv.x;
            KP[(lc4 + 1) * 64 + row] = kv.y;
            KP[(lc4 + 2) * 64 + row] = kv.z;
            KP[(lc4 + 3) * 64 + row] = kv.w;
            float4 vv = *(const float4*)(vtile + row * DH_ + lc4);
            *(float4*)(Vs + row * 64 + lc4) = vv;
        }
        __syncthreads();

        // S = Q @ K^T * 0.125
        float sc[4][4] = {};
#pragma unroll 8
        for (int d = 0; d < DH_; d++) {
            float4 qv = *(const float4*)(Qt + d * 64 + ty * 4);
            float4 kv = *(const float4*)(KP + d * 64 + tx * 4);
            float qa[4] = {qv.x, qv.y, qv.z, qv.w};
            float ka[4] = {kv.x, kv.y, kv.z, kv.w};
#pragma unroll
            for (int i = 0; i < 4; i++)
#pragma unroll
                for (int j = 0; j < 4; j++)
                    sc[i][j] = fmaf(qa[i], ka[j], sc[i][j]);
        }

        // Online softmax (row stats across the 16 tx lanes; contiguous in warp)
#pragma unroll
        for (int i = 0; i < 4; i++) {
            float mx = -1e30f;
#pragma unroll
            for (int j = 0; j < 4; j++) {
                sc[i][j] *= 0.125f;
                mx = fmaxf(mx, sc[i][j]);
            }
#pragma unroll
            for (int off = 1; off < 16; off <<= 1)
                mx = fmaxf(mx, __shfl_xor_sync(0xffffffffu, mx, off));
            float mnew = fmaxf(mi[i], mx);
            float corr = __expf(mi[i] - mnew);
            float psum = 0.f;
#pragma unroll
            for (int j = 0; j < 4; j++) {
                sc[i][j] = __expf(sc[i][j] - mnew);
                psum += sc[i][j];
            }
#pragma unroll
            for (int off = 1; off < 16; off <<= 1)
                psum += __shfl_xor_sync(0xffffffffu, psum, off);
            li[i] = li[i] * corr + psum;
            mi[i] = mnew;
#pragma unroll
            for (int j = 0; j < 4; j++) accO[i][j] *= corr;
        }

        __syncthreads();  // all K reads done before P overwrites the buffer
        // P^T into KP: Pt[k*64 + q]
#pragma unroll
        for (int j = 0; j < 4; j++)
#pragma unroll
            for (int i = 0; i < 4; i++)
                KP[(tx * 4 + j) * 64 + (ty * 4 + i)] = sc[i][j];
        __syncthreads();

        // accO += P @ V
#pragma unroll 8
        for (int k = 0; k < 64; k++) {
            float4 pv = *(const float4*)(KP + k * 64 + ty * 4);
            float4 vv = *(const float4*)(Vs + k * 64 + tx * 4);
            float pa[4] = {pv.x, pv.y, pv.z, pv.w};
            float va[4] = {vv.x, vv.y, vv.z, vv.w};
#pragma unroll
            for (int i = 0; i < 4; i++)
#pragma unroll
                for (int j = 0; j < 4; j++)
                    accO[i][j] = fmaf(pa[i], va[j], accO[i][j]);
        }
    }

    // Epilogue: ctx in [B, S, H*Dh] row-major for the output projection
#pragma unroll
    for (int i = 0; i < 4; i++) {
        float inv = 1.f / li[i];
        int s = q0 + ty * 4 + i;
        float4 o = make_float4(accO[i][0] * inv, accO[i][1] * inv,
                               accO[i][2] * inv, accO[i][3] * inv);
        *(float4*)(g_ctx + (batch * S_ + s) * DM_ + head * DH_ + tx * 4) = o;
    }
}

// ---------------- Kernel 3: output projection ----------------
__global__ void __launch_bounds__(256) proj_kernel(
    const float* __restrict__ Wc, const float* __restrict__ bc,
    float* __restrict__ out)
{
    __shared__ __align__(16) float Asm[BK * ASTRIDE];
    __shared__ __align__(16) float Bsm[BK * ASTRIDE];

    const int m0 = blockIdx.x * BM;
    const int n0 = blockIdx.y * BN;
    float acc[4][4] = {};
    gemm_core(g_ctx, Wc, Asm, Bsm, m0, n0, acc);

    const int ty = threadIdx.x >> 4, tx = threadIdx.x & 15;
    float4 bb = *(const float4*)(bc + n0 + tx * 4);
#pragma unroll
    for (int i = 0; i < 4; i++) {
        int m = m0 + ty * 4 + i;
        float4 o = make_float4(acc[i][0] + bb.x, acc[i][1] + bb.y,
                               acc[i][2] + bb.z, acc[i][3] + bb.w);
        *(float4*)(out + (size_t)m * DM_ + n0 + tx * 4) = o;
    }
}

// ---------------- Launch ----------------
extern "C" void kernel_launch(void* const* d_in, const int* in_sizes, int n_in,
                              void* d_out, int out_size)
{
    const float* x  = (const float*)d_in[0];
    const float* Wq = (const float*)d_in[1];
    const float* bq = (const float*)d_in[2];
    const float* Wk = (const float*)d_in[3];
    const float* bk = (const float*)d_in[4];
    const float* Wv = (const float*)d_in[5];
    const float* bv = (const float*)d_in[6];
    const float* Wc = (const float*)d_in[7];
    const float* bc = (const float*)d_in[8];
    float* out = (float*)d_out;

    dim3 gq(MTOT / BM, DM_ / BN, 3);       // 256 x 12 x 3
    qkv_kernel<<<gq, 256>>>(x, Wq, bq, Wk, bk, Wv, bv);

    dim3 ga(S_ / 64, H_, B_);              // 16 x 12 x 16
    attn_kernel<<<ga, 256>>>();

    dim3 gp(MTOT / BM, DM_ / BN);          // 256 x 12
    proj_kernel<<<gp, 256>>>(Wc, bc, out);
}

// round 2
// speedup vs baseline: 2.6069x; 2.6069x over previous
#include <cuda_runtime.h>
#include <cstdint>

#define B_   16
#define S_   1024
#define DM_  768
#define H_   12
#define DH_  64
#define MTOT (B_ * S_)   // 16384
#define WSZ  589824      // 768*768

// Scratch (allocation-free rule: __device__ globals)
__device__ float g_q[(size_t)B_ * H_ * S_ * DH_];
__device__ float g_k[(size_t)B_ * H_ * S_ * DH_];
__device__ float g_v[(size_t)B_ * H_ * S_ * DH_];
__device__ float g_ctx[(size_t)B_ * S_ * DM_];
__device__ float g_xr[(size_t)MTOT * DM_];    // tf32-rounded x
__device__ float g_wr[(size_t)4 * WSZ];       // tf32-rounded Wq,Wk,Wv,Wc

// ---------------- helpers ----------------
__device__ __forceinline__ float tf32r(float x) {
    uint32_t u;
    asm("cvt.rna.tf32.f32 %0, %1;" : "=r"(u) : "f"(x));
    return __uint_as_float(u);
}

__device__ __forceinline__ void mma_tf32(float c[4],
                                         uint32_t a0, uint32_t a1, uint32_t a2, uint32_t a3,
                                         uint32_t b0, uint32_t b1) {
    asm volatile(
        "mma.sync.aligned.m16n8k8.row.col.f32.tf32.tf32.f32 "
        "{%0,%1,%2,%3}, {%4,%5,%6,%7}, {%8,%9}, {%0,%1,%2,%3};"
        : "+f"(c[0]), "+f"(c[1]), "+f"(c[2]), "+f"(c[3])
        : "r"(a0), "r"(a1), "r"(a2), "r"(a3), "r"(b0), "r"(b1));
}

// ---------------- rounding pass ----------------
__global__ void round_tf32_kernel(const float4* __restrict__ src,
                                  float4* __restrict__ dst, int n4) {
    int i = blockIdx.x * blockDim.x + threadIdx.x;
    if (i < n4) {
        float4 v = src[i];
        v.x = tf32r(v.x); v.y = tf32r(v.y); v.z = tf32r(v.z); v.w = tf32r(v.w);
        dst[i] = v;
    }
}

// ---------------- tensor-core GEMM core ----------------
// Y[m,n] = sum_k A[m,k] * W[n,k].  Block 128x128, k-step 32, 256 threads.
// Warps: 2(m) x 4(n); warp tile 64x32 = 4x4 m16n8k8 atoms.
// Smem holds operands pre-swizzled into mma fragment layout:
//   Af tile (mt,ks): 32 lanes x 4 regs, tile stride 132 (pad kills bank conflicts)
//   Bf tile (nt,ks): 32 lanes x 2 regs, tile stride 68
#define GBK 32
#define AF_TILES 32   // 8 mtiles * 4 ks
#define BF_TILES 64   // 16 ntiles * 4 ks
#define AF_STRIDE 132
#define BF_STRIDE 68

__device__ __forceinline__ void tc_gemm_core(const float* __restrict__ A,
                                             const float* __restrict__ W,
                                             int m0, int n0,
                                             uint32_t* Af, uint32_t* Bf,
                                             float acc[4][4][4])
{
    const int tid  = threadIdx.x;
    const int lane = tid & 31;
    const int wid  = tid >> 5;
    const int wm   = wid >> 2;   // 0..1
    const int wn   = wid & 3;    // 0..3

    for (int kt = 0; kt < DM_; kt += GBK) {
        // -------- global loads (before sync, overlap with prior compute) -----
        float4 av[4], wv[4];
#pragma unroll
        for (int i = 0; i < 4; i++) {
            int f4  = tid + (i << 8);      // 0..1023
            int row = f4 >> 3;             // 0..127
            int kc  = (f4 & 7) << 2;       // 0,4,...,28
            av[i] = *(const float4*)(A + (size_t)(m0 + row) * DM_ + kt + kc);
            wv[i] = *(const float4*)(W + (size_t)(n0 + row) * DM_ + kt + kc);
        }
        __syncthreads();
        // -------- scatter into fragment layout ------------------------------
#pragma unroll
        for (int i = 0; i < 4; i++) {
            int f4  = tid + (i << 8);
            int row = f4 >> 3;
            int kc  = (f4 & 7) << 2;
            int ks  = kc >> 3;             // 0..3
            int chi = (kc & 7) >> 2;       // c>=4 half?
            const float* pa = (const float*)&av[i];
            const float* pw = (const float*)&wv[i];
            {   // A: a-frag: lane=(r%8)*4 + c%4, reg=(r/8) + 2*(c/4)
                int mt = row >> 4, rr = row & 15;
                int lb = (rr & 7) << 2;
                int rg = (rr >> 3) + (chi << 1);
                uint32_t* dst = Af + ((mt << 2) + ks) * AF_STRIDE;
#pragma unroll
                for (int j = 0; j < 4; j++)
                    dst[((lb + j) << 2) + rg] = __float_as_uint(pa[j]);
            }
            {   // B: b-frag: lane=(n%8)*4 + k%4, reg=k/4
                int nt = row >> 3, ln = row & 7;
                int lb = ln << 2;
                uint32_t* dst = Bf + ((nt << 2) + ks) * BF_STRIDE;
#pragma unroll
                for (int j = 0; j < 4; j++)
                    dst[((lb + j) << 1) + chi] = __float_as_uint(pw[j]);
            }
        }
        __syncthreads();
        // -------- compute ---------------------------------------------------
#pragma unroll
        for (int ks = 0; ks < 4; ks++) {
            uint4 a[4]; uint2 b[4];
#pragma unroll
            for (int mi = 0; mi < 4; mi++)
                a[mi] = *(const uint4*)(Af + (((wm * 4 + mi) * 4 + ks)) * AF_STRIDE + (lane << 2));
#pragma unroll
            for (int ni = 0; ni < 4; ni++)
                b[ni] = *(const uint2*)(Bf + (((wn * 4 + ni) * 4 + ks)) * BF_STRIDE + (lane << 1));
#pragma unroll
            for (int mi = 0; mi < 4; mi++)
#pragma unroll
                for (int ni = 0; ni < 4; ni++)
                    mma_tf32(acc[mi][ni], a[mi].x, a[mi].y, a[mi].z, a[mi].w,
                             b[ni].x, b[ni].y);
        }
    }
}

// ---------------- Kernel 1: fused QKV projection (tensor core) ----------------
// grid = (MTOT/128, 768/128 = 6, 3). Output layout [B, H, S, Dh].
__global__ void __launch_bounds__(256) qkv_tc_kernel(
    const float* __restrict__ bq, const float* __restrict__ bk,
    const float* __restrict__ bv)
{
    __shared__ __align__(16) uint32_t Af[AF_TILES * AF_STRIDE];
    __shared__ __align__(16) uint32_t Bf[BF_TILES * BF_STRIDE];

    const int which = blockIdx.z;
    const float* W    = g_wr + (size_t)which * WSZ;
    const float* bias = (which == 0) ? bq : (which == 1) ? bk : bv;
    float* out        = (which == 0) ? g_q : (which == 1) ? g_k : g_v;

    const int m0 = blockIdx.x * 128;
    const int n0 = blockIdx.y * 128;
    float acc[4][4][4] = {};
    tc_gemm_core(g_xr, W, m0, n0, Af, Bf, acc);

    const int lane = threadIdx.x & 31;
    const int wid  = threadIdx.x >> 5;
    const int wm = wid >> 2, wn = wid & 3;
#pragma unroll
    for (int mi = 0; mi < 4; mi++) {
        int r0 = m0 + wm * 64 + mi * 16 + (lane >> 2);
#pragma unroll
        for (int ni = 0; ni < 4; ni++) {
            int n  = n0 + wn * 32 + ni * 8 + ((lane & 3) << 1);
            float b0 = bias[n], b1 = bias[n + 1];
            int h = n >> 6, d = n & 63;
#pragma unroll
            for (int rr = 0; rr < 2; rr++) {
                int m = r0 + rr * 8;
                int bb = m >> 10, s = m & 1023;
                float2 o = make_float2(acc[mi][ni][rr * 2 + 0] + b0,
                                       acc[mi][ni][rr * 2 + 1] + b1);
                *(float2*)(out + (((size_t)(bb * H_ + h) * S_ + s) * DH_ + d)) = o;
            }
        }
    }
}

// ---------------- Kernel 3: output projection (tensor core) ----------------
__global__ void __launch_bounds__(256) proj_tc_kernel(
    const float* __restrict__ bc, float* __restrict__ out)
{
    __shared__ __align__(16) uint32_t Af[AF_TILES * AF_STRIDE];
    __shared__ __align__(16) uint32_t Bf[BF_TILES * BF_STRIDE];

    const int m0 = blockIdx.x * 128;
    const int n0 = blockIdx.y * 128;
    float acc[4][4][4] = {};
    tc_gemm_core(g_ctx, g_wr + (size_t)3 * WSZ, m0, n0, Af, Bf, acc);

    const int lane = threadIdx.x & 31;
    const int wid  = threadIdx.x >> 5;
    const int wm = wid >> 2, wn = wid & 3;
#pragma unroll
    for (int mi = 0; mi < 4; mi++) {
        int r0 = m0 + wm * 64 + mi * 16 + (lane >> 2);
#pragma unroll
        for (int ni = 0; ni < 4; ni++) {
            int n  = n0 + wn * 32 + ni * 8 + ((lane & 3) << 1);
            float b0 = bc[n], b1 = bc[n + 1];
#pragma unroll
            for (int rr = 0; rr < 2; rr++) {
                int m = r0 + rr * 8;
                float2 o = make_float2(acc[mi][ni][rr * 2 + 0] + b0,
                                       acc[mi][ni][rr * 2 + 1] + b1);
                *(float2*)(out + (size_t)m * DM_ + n) = o;
            }
        }
    }
}

// ---------------- Kernel 2: flash attention (fp32, unchanged math) ----------------
__global__ void __launch_bounds__(256) attn_kernel()
{
    __shared__ __align__(16) float Qt[64 * 64];  // Qt[d*64 + q]
    __shared__ __align__(16) float KP[64 * 64];  // Kt[d*64 + k]  /  Pt[k*64 + q]
    __shared__ __align__(16) float Vs[64 * 64];  // Vs[k*64 + d]

    const int tid  = threadIdx.x;
    const int ty   = tid >> 4, tx = tid & 15;
    const int q0   = blockIdx.x * 64;
    const int head = blockIdx.y, batch = blockIdx.z;
    const int base = ((batch * H_ + head) * S_) * DH_;
    const float* qb = g_q + base;
    const float* kb = g_k + base;
    const float* vb = g_v + base;

    const int lr16 = tid >> 4;
    const int lc4  = (tid & 15) * 4;

#pragma unroll
    for (int r = 0; r < 4; r++) {
        int row = lr16 + r * 16;
        float4 v = *(const float4*)(qb + (q0 + row) * DH_ + lc4);
        Qt[(lc4 + 0) * 64 + row] = v.x;
        Qt[(lc4 + 1) * 64 + row] = v.y;
        Qt[(lc4 + 2) * 64 + row] = v.z;
        Qt[(lc4 + 3) * 64 + row] = v.w;
    }

    float mi[4], li[4], accO[4][4];
#pragma unroll
    for (int i = 0; i < 4; i++) {
        mi[i] = -1e30f; li[i] = 0.f;
#pragma unroll
        for (int j = 0; j < 4; j++) accO[i][j] = 0.f;
    }

    for (int t = 0; t < S_ / 64; t++) {
        const float* ktile = kb + t * 64 * DH_;
        const float* vtile = vb + t * 64 * DH_;
        __syncthreads();
#pragma unroll
        for (int r = 0; r < 4; r++) {
            int row = lr16 + r * 16;
            float4 kv = *(const float4*)(ktile + row * DH_ + lc4);
            KP[(lc4 + 0) * 64 + row] = kv.x;
            KP[(lc4 + 1) * 64 + row] = kv.y;
            KP[(lc4 + 2) * 64 + row] = kv.z;
            KP[(lc4 + 3) * 64 + row] = kv.w;
            float4 vv = *(const float4*)(vtile + row * DH_ + lc4);
            *(float4*)(Vs + row * 64 + lc4) = vv;
        }
        __syncthreads();

        float sc[4][4] = {};
#pragma unroll 8
        for (int d = 0; d < DH_; d++) {
            float4 qv = *(const float4*)(Qt + d * 64 + ty * 4);
            float4 kv = *(const float4*)(KP + d * 64 + tx * 4);
            float qa[4] = {qv.x, qv.y, qv.z, qv.w};
            float ka[4] = {kv.x, kv.y, kv.z, kv.w};
#pragma unroll
            for (int i = 0; i < 4; i++)
#pragma unroll
                for (int j = 0; j < 4; j++)
                    sc[i][j] = fmaf(qa[i], ka[j], sc[i][j]);
        }

#pragma unroll
        for (int i = 0; i < 4; i++) {
            float mx = -1e30f;
#pragma unroll
            for (int j = 0; j < 4; j++) {
                sc[i][j] *= 0.125f;
                mx = fmaxf(mx, sc[i][j]);
            }
#pragma unroll
            for (int off = 1; off < 16; off <<= 1)
                mx = fmaxf(mx, __shfl_xor_sync(0xffffffffu, mx, off));
            float mnew = fmaxf(mi[i], mx);
            float corr = __expf(mi[i] - mnew);
            float psum = 0.f;
#pragma unroll
            for (int j = 0; j < 4; j++) {
                sc[i][j] = __expf(sc[i][j] - mnew);
                psum += sc[i][j];
            }
#pragma unroll
            for (int off = 1; off < 16; off <<= 1)
                psum += __shfl_xor_sync(0xffffffffu, psum, off);
            li[i] = li[i] * corr + psum;
            mi[i] = mnew;
#pragma unroll
            for (int j = 0; j < 4; j++) accO[i][j] *= corr;
        }

        __syncthreads();
#pragma unroll
        for (int j = 0; j < 4; j++)
#pragma unroll
            for (int i = 0; i < 4; i++)
                KP[(tx * 4 + j) * 64 + (ty * 4 + i)] = sc[i][j];
        __syncthreads();

#pragma unroll 8
        for (int k = 0; k < 64; k++) {
            float4 pv = *(const float4*)(KP + k * 64 + ty * 4);
            float4 vv = *(const float4*)(Vs + k * 64 + tx * 4);
            float pa[4] = {pv.x, pv.y, pv.z, pv.w};
            float va[4] = {vv.x, vv.y, vv.z, vv.w};
#pragma unroll
            for (int i = 0; i < 4; i++)
#pragma unroll
                for (int j = 0; j < 4; j++)
                    accO[i][j] = fmaf(pa[i], va[j], accO[i][j]);
        }
    }

    // Epilogue: tf32-round ctx so the output projection sees RN-rounded inputs
#pragma unroll
    for (int i = 0; i < 4; i++) {
        float inv = 1.f / li[i];
        int s = q0 + ty * 4 + i;
        float4 o = make_float4(tf32r(accO[i][0] * inv), tf32r(accO[i][1] * inv),
                               tf32r(accO[i][2] * inv), tf32r(accO[i][3] * inv));
        *(float4*)(g_ctx + (batch * S_ + s) * DM_ + head * DH_ + tx * 4) = o;
    }
}

// ---------------- Launch ----------------
extern "C" void kernel_launch(void* const* d_in, const int* in_sizes, int n_in,
                              void* d_out, int out_size)
{
    const float* x  = (const float*)d_in[0];
    const float* Wq = (const float*)d_in[1];
    const float* bq = (const float*)d_in[2];
    const float* Wk = (const float*)d_in[3];
    const float* bk = (const float*)d_in[4];
    const float* Wv = (const float*)d_in[5];
    const float* bv = (const float*)d_in[6];
    const float* Wc = (const float*)d_in[7];
    const float* bc = (const float*)d_in[8];
    float* out = (float*)d_out;

    float* xr; cudaGetSymbolAddress((void**)&xr, g_xr);
    float* wr; cudaGetSymbolAddress((void**)&wr, g_wr);

    // tf32 RN pre-rounding (unbiased; raw truncation would bias results)
    int nx4 = MTOT * DM_ / 4;
    int nw4 = WSZ / 4;
    round_tf32_kernel<<<(nx4 + 255) / 256, 256>>>((const float4*)x,  (float4*)xr, nx4);
    round_tf32_kernel<<<(nw4 + 255) / 256, 256>>>((const float4*)Wq, (float4*)(wr + 0 * (size_t)WSZ), nw4);
    round_tf32_kernel<<<(nw4 + 255) / 256, 256>>>((const float4*)Wk, (float4*)(wr + 1 * (size_t)WSZ), nw4);
    round_tf32_kernel<<<(nw4 + 255) / 256, 256>>>((const float4*)Wv, (float4*)(wr + 2 * (size_t)WSZ), nw4);
    round_tf32_kernel<<<(nw4 + 255) / 256, 256>>>((const float4*)Wc, (float4*)(wr + 3 * (size_t)WSZ), nw4);

    dim3 gq(MTOT / 128, DM_ / 128, 3);     // 128 x 6 x 3
    qkv_tc_kernel<<<gq, 256>>>(bq, bk, bv);

    dim3 ga(S_ / 64, H_, B_);              // 16 x 12 x 16
    attn_kernel<<<ga, 256>>>();

    dim3 gp(MTOT / 128, DM_ / 128);        // 128 x 6
    proj_tc_kernel<<<gp, 256>>>(bc, out);
}

// round 3
// speedup vs baseline: 5.4523x; 2.0915x over previous
#include <cuda_runtime.h>
#include <cstdint>

#define B_   16
#define S_   1024
#define DM_  768
#define H_   12
#define DH_  64
#define MTOT (B_ * S_)   // 16384
#define WSZ  589824      // 768*768

// Scratch (allocation-free rule: __device__ globals)
__device__ float g_q[(size_t)B_ * H_ * S_ * DH_];
__device__ float g_k[(size_t)B_ * H_ * S_ * DH_];
__device__ float g_v[(size_t)B_ * H_ * S_ * DH_];
__device__ float g_ctx[(size_t)B_ * S_ * DM_];
__device__ float g_xr[(size_t)MTOT * DM_];    // tf32-rounded x
__device__ float g_wr[(size_t)4 * WSZ];       // tf32-rounded Wq,Wk,Wv,Wc

// ---------------- helpers ----------------
__device__ __forceinline__ float tf32r(float x) {
    uint32_t u;
    asm("cvt.rna.tf32.f32 %0, %1;" : "=r"(u) : "f"(x));
    return __uint_as_float(u);
}

__device__ __forceinline__ void mma_tf32(float c[4],
                                         uint32_t a0, uint32_t a1, uint32_t a2, uint32_t a3,
                                         uint32_t b0, uint32_t b1) {
    asm volatile(
        "mma.sync.aligned.m16n8k8.row.col.f32.tf32.tf32.f32 "
        "{%0,%1,%2,%3}, {%4,%5,%6,%7}, {%8,%9}, {%0,%1,%2,%3};"
        : "+f"(c[0]), "+f"(c[1]), "+f"(c[2]), "+f"(c[3])
        : "r"(a0), "r"(a1), "r"(a2), "r"(a3), "r"(b0), "r"(b1));
}

// ---------------- rounding pass ----------------
__global__ void round_tf32_kernel(const float4* __restrict__ src,
                                  float4* __restrict__ dst, int n4) {
    int i = blockIdx.x * blockDim.x + threadIdx.x;
    if (i < n4) {
        float4 v = src[i];
        v.x = tf32r(v.x); v.y = tf32r(v.y); v.z = tf32r(v.z); v.w = tf32r(v.w);
        dst[i] = v;
    }
}

// ---------------- tensor-core GEMM core (unchanged from R2) ----------------
#define GBK 32
#define AF_TILES 32
#define BF_TILES 64
#define AF_STRIDE 132
#define BF_STRIDE 68

__device__ __forceinline__ void tc_gemm_core(const float* __restrict__ A,
                                             const float* __restrict__ W,
                                             int m0, int n0,
                                             uint32_t* Af, uint32_t* Bf,
                                             float acc[4][4][4])
{
    const int tid  = threadIdx.x;
    const int lane = tid & 31;
    const int wid  = tid >> 5;
    const int wm   = wid >> 2;
    const int wn   = wid & 3;

    for (int kt = 0; kt < DM_; kt += GBK) {
        float4 av[4], wv[4];
#pragma unroll
        for (int i = 0; i < 4; i++) {
            int f4  = tid + (i << 8);
            int row = f4 >> 3;
            int kc  = (f4 & 7) << 2;
            av[i] = *(const float4*)(A + (size_t)(m0 + row) * DM_ + kt + kc);
            wv[i] = *(const float4*)(W + (size_t)(n0 + row) * DM_ + kt + kc);
        }
        __syncthreads();
#pragma unroll
        for (int i = 0; i < 4; i++) {
            int f4  = tid + (i << 8);
            int row = f4 >> 3;
            int kc  = (f4 & 7) << 2;
            int ks  = kc >> 3;
            int chi = (kc & 7) >> 2;
            const float* pa = (const float*)&av[i];
            const float* pw = (const float*)&wv[i];
            {
                int mt = row >> 4, rr = row & 15;
                int lb = (rr & 7) << 2;
                int rg = (rr >> 3) + (chi << 1);
                uint32_t* dst = Af + ((mt << 2) + ks) * AF_STRIDE;
#pragma unroll
                for (int j = 0; j < 4; j++)
                    dst[((lb + j) << 2) + rg] = __float_as_uint(pa[j]);
            }
            {
                int nt = row >> 3, ln = row & 7;
                int lb = ln << 2;
                uint32_t* dst = Bf + ((nt << 2) + ks) * BF_STRIDE;
#pragma unroll
                for (int j = 0; j < 4; j++)
                    dst[((lb + j) << 1) + chi] = __float_as_uint(pw[j]);
            }
        }
        __syncthreads();
#pragma unroll
        for (int ks = 0; ks < 4; ks++) {
            uint4 a[4]; uint2 b[4];
#pragma unroll
            for (int mi = 0; mi < 4; mi++)
                a[mi] = *(const uint4*)(Af + (((wm * 4 + mi) * 4 + ks)) * AF_STRIDE + (lane << 2));
#pragma unroll
            for (int ni = 0; ni < 4; ni++)
                b[ni] = *(const uint2*)(Bf + (((wn * 4 + ni) * 4 + ks)) * BF_STRIDE + (lane << 1));
#pragma unroll
            for (int mi = 0; mi < 4; mi++)
#pragma unroll
                for (int ni = 0; ni < 4; ni++)
                    mma_tf32(acc[mi][ni], a[mi].x, a[mi].y, a[mi].z, a[mi].w,
                             b[ni].x, b[ni].y);
        }
    }
}

// ---------------- Kernel 1: fused QKV projection ----------------
// Outputs tf32-RN-rounded q/k/v so attention reads pre-rounded operands.
__global__ void __launch_bounds__(256) qkv_tc_kernel(
    const float* __restrict__ bq, const float* __restrict__ bk,
    const float* __restrict__ bv)
{
    __shared__ __align__(16) uint32_t Af[AF_TILES * AF_STRIDE];
    __shared__ __align__(16) uint32_t Bf[BF_TILES * BF_STRIDE];

    const int which = blockIdx.z;
    const float* W    = g_wr + (size_t)which * WSZ;
    const float* bias = (which == 0) ? bq : (which == 1) ? bk : bv;
    float* out        = (which == 0) ? g_q : (which == 1) ? g_k : g_v;

    const int m0 = blockIdx.x * 128;
    const int n0 = blockIdx.y * 128;
    float acc[4][4][4] = {};
    tc_gemm_core(g_xr, W, m0, n0, Af, Bf, acc);

    const int lane = threadIdx.x & 31;
    const int wid  = threadIdx.x >> 5;
    const int wm = wid >> 2, wn = wid & 3;
#pragma unroll
    for (int mi = 0; mi < 4; mi++) {
        int r0 = m0 + wm * 64 + mi * 16 + (lane >> 2);
#pragma unroll
        for (int ni = 0; ni < 4; ni++) {
            int n  = n0 + wn * 32 + ni * 8 + ((lane & 3) << 1);
            float b0 = bias[n], b1 = bias[n + 1];
            int h = n >> 6, d = n & 63;
#pragma unroll
            for (int rr = 0; rr < 2; rr++) {
                int m = r0 + rr * 8;
                int bb = m >> 10, s = m & 1023;
                float2 o = make_float2(tf32r(acc[mi][ni][rr * 2 + 0] + b0),
                                       tf32r(acc[mi][ni][rr * 2 + 1] + b1));
                *(float2*)(out + (((size_t)(bb * H_ + h) * S_ + s) * DH_ + d)) = o;
            }
        }
    }
}

// ---------------- Kernel 3: output projection ----------------
__global__ void __launch_bounds__(256) proj_tc_kernel(
    const float* __restrict__ bc, float* __restrict__ out)
{
    __shared__ __align__(16) uint32_t Af[AF_TILES * AF_STRIDE];
    __shared__ __align__(16) uint32_t Bf[BF_TILES * BF_STRIDE];

    const int m0 = blockIdx.x * 128;
    const int n0 = blockIdx.y * 128;
    float acc[4][4][4] = {};
    tc_gemm_core(g_ctx, g_wr + (size_t)3 * WSZ, m0, n0, Af, Bf, acc);

    const int lane = threadIdx.x & 31;
    const int wid  = threadIdx.x >> 5;
    const int wm = wid >> 2, wn = wid & 3;
#pragma unroll
    for (int mi = 0; mi < 4; mi++) {
        int r0 = m0 + wm * 64 + mi * 16 + (lane >> 2);
#pragma unroll
        for (int ni = 0; ni < 4; ni++) {
            int n  = n0 + wn * 32 + ni * 8 + ((lane & 3) << 1);
            float b0 = bc[n], b1 = bc[n + 1];
#pragma unroll
            for (int rr = 0; rr < 2; rr++) {
                int m = r0 + rr * 8;
                float2 o = make_float2(acc[mi][ni][rr * 2 + 0] + b0,
                                       acc[mi][ni][rr * 2 + 1] + b1);
                *(float2*)(out + (size_t)m * DM_ + n) = o;
            }
        }
    }
}

// ---------------- Kernel 2: flash attention (tensor core, tf32) ----------------
// Block = 128 queries for one (b,h). 8 warps; warp owns 16 query rows.
// Smem (dynamic): X[128][68] = K tile (rows 0..63) then P; Vt[64][68] = V^T.
// Stride 68 == 4 (mod 32) -> conflict-free fragment reads for QK-b, PV-a, PV-b.
#define ATS 68
#define ATT_SMEM ((128 + 64) * ATS * 4)   // 52224 bytes

__global__ void __launch_bounds__(256) attn_tc_kernel()
{
    extern __shared__ float sm[];
    float* X  = sm;              // K [64][ATS] -> P [128][ATS]
    float* Vt = sm + 128 * ATS;  // V^T [d][key], [64][ATS]

    const int tid  = threadIdx.x;
    const int lane = tid & 31, w = tid >> 5;
    const int r = lane >> 2, c = lane & 3;
    const int q0   = blockIdx.x * 128;
    const int head = blockIdx.y, batch = blockIdx.z;
    const size_t base = ((size_t)(batch * H_ + head) * S_) * DH_;
    const float* qb = g_q + base;
    const float* kb = g_k + base;
    const float* vb = g_v + base;

    // Q a-fragments held in registers for the whole kernel (pre-rounded by qkv)
    uint32_t qa[8][4];
    {
        const float* qlo = qb + (size_t)(q0 + w * 16 + r) * DH_;
        const float* qhi = qlo + 8 * DH_;
#pragma unroll
        for (int ks = 0; ks < 8; ks++) {
            qa[ks][0] = __float_as_uint(qlo[ks * 8 + c]);
            qa[ks][1] = __float_as_uint(qhi[ks * 8 + c]);
            qa[ks][2] = __float_as_uint(qlo[ks * 8 + c + 4]);
            qa[ks][3] = __float_as_uint(qhi[ks * 8 + c + 4]);
        }
    }

    float o[8][4];
#pragma unroll
    for (int a = 0; a < 8; a++)
#pragma unroll
        for (int j = 0; j < 4; j++) o[a][j] = 0.f;
    float mi0 = -1e30f, mi1 = -1e30f, li0 = 0.f, li1 = 0.f;

    for (int t = 0; t < S_ / 64; t++) {
        __syncthreads();   // prior PV reads of X/Vt complete
        {
            const float* kt = kb + (size_t)t * 64 * DH_;
            const float* vt = vb + (size_t)t * 64 * DH_;
#pragma unroll
            for (int i = 0; i < 4; i++) {
                int f   = tid + (i << 8);      // 0..1023 float4s
                int row = f >> 4;              // 0..63 (key)
                int col = (f & 15) << 2;       // 0..60 (d)
                float4 kv = *(const float4*)(kt + row * DH_ + col);
                X[row * ATS + col + 0] = kv.x;
                X[row * ATS + col + 1] = kv.y;
                X[row * ATS + col + 2] = kv.z;
                X[row * ATS + col + 3] = kv.w;
                float4 vv = *(const float4*)(vt + row * DH_ + col);
                Vt[(col + 0) * ATS + row] = vv.x;
                Vt[(col + 1) * ATS + row] = vv.y;
                Vt[(col + 2) * ATS + row] = vv.z;
                Vt[(col + 3) * ATS + row] = vv.w;
            }
        }
        __syncthreads();

        // ---- S = Q @ K^T ----
        float s[8][4];
#pragma unroll
        for (int a = 0; a < 8; a++)
#pragma unroll
            for (int j = 0; j < 4; j++) s[a][j] = 0.f;
#pragma unroll
        for (int ks = 0; ks < 8; ks++) {
#pragma unroll
            for (int a = 0; a < 8; a++) {
                const float* kp = X + (a * 8 + r) * ATS + ks * 8 + c;
                uint32_t b0 = __float_as_uint(kp[0]);
                uint32_t b1 = __float_as_uint(kp[4]);
                mma_tf32(s[a], qa[ks][0], qa[ks][1], qa[ks][2], qa[ks][3], b0, b1);
            }
        }

        // ---- online softmax (rows r and r+8; quad-local reductions) ----
        float mx0 = -1e30f, mx1 = -1e30f;
#pragma unroll
        for (int a = 0; a < 8; a++) {
            s[a][0] *= 0.125f; s[a][1] *= 0.125f;
            s[a][2] *= 0.125f; s[a][3] *= 0.125f;
            mx0 = fmaxf(mx0, fmaxf(s[a][0], s[a][1]));
            mx1 = fmaxf(mx1, fmaxf(s[a][2], s[a][3]));
        }
        mx0 = fmaxf(mx0, __shfl_xor_sync(0xffffffffu, mx0, 1));
        mx0 = fmaxf(mx0, __shfl_xor_sync(0xffffffffu, mx0, 2));
        mx1 = fmaxf(mx1, __shfl_xor_sync(0xffffffffu, mx1, 1));
        mx1 = fmaxf(mx1, __shfl_xor_sync(0xffffffffu, mx1, 2));
        float mn0 = fmaxf(mi0, mx0), mn1 = fmaxf(mi1, mx1);
        float cr0 = __expf(mi0 - mn0), cr1 = __expf(mi1 - mn1);
        float sum0 = 0.f, sum1 = 0.f;
#pragma unroll
        for (int a = 0; a < 8; a++) {
            s[a][0] = __expf(s[a][0] - mn0);
            s[a][1] = __expf(s[a][1] - mn0);
            s[a][2] = __expf(s[a][2] - mn1);
            s[a][3] = __expf(s[a][3] - mn1);
            sum0 += s[a][0] + s[a][1];
            sum1 += s[a][2] + s[a][3];
        }
        sum0 += __shfl_xor_sync(0xffffffffu, sum0, 1);
        sum0 += __shfl_xor_sync(0xffffffffu, sum0, 2);
        sum1 += __shfl_xor_sync(0xffffffffu, sum1, 1);
        sum1 += __shfl_xor_sync(0xffffffffu, sum1, 2);
        li0 = li0 * cr0 + sum0;  mi0 = mn0;
        li1 = li1 * cr1 + sum1;  mi1 = mn1;
#pragma unroll
        for (int a = 0; a < 8; a++) {
            o[a][0] *= cr0; o[a][1] *= cr0;
            o[a][2] *= cr1; o[a][3] *= cr1;
        }

        __syncthreads();   // all warps done reading K before P overwrites X
        {
            float* pr = X + (w * 16 + r) * ATS;
#pragma unroll
            for (int a = 0; a < 8; a++) {
                *(float2*)(pr + a * 8 + 2 * c) =
                    make_float2(tf32r(s[a][0]), tf32r(s[a][1]));
                *(float2*)(pr + 8 * ATS + a * 8 + 2 * c) =
                    make_float2(tf32r(s[a][2]), tf32r(s[a][3]));
            }
        }
        __syncthreads();

        // ---- O += P @ V ----
        const float* pw = X + (w * 16) * ATS;
#pragma unroll
        for (int ks = 0; ks < 8; ks++) {
            uint32_t a0 = __float_as_uint(pw[r * ATS + ks * 8 + c]);
            uint32_t a1 = __float_as_uint(pw[(r + 8) * ATS + ks * 8 + c]);
            uint32_t a2 = __float_as_uint(pw[r * ATS + ks * 8 + c + 4]);
            uint32_t a3 = __float_as_uint(pw[(r + 8) * ATS + ks * 8 + c + 4]);
#pragma unroll
            for (int a = 0; a < 8; a++) {
                const float* vp = Vt + (a * 8 + r) * ATS + ks * 8 + c;
                uint32_t b0 = __float_as_uint(vp[0]);
                uint32_t b1 = __float_as_uint(vp[4]);
                mma_tf32(o[a], a0, a1, a2, a3, b0, b1);
            }
        }
    }

    // ---- epilogue: normalize, tf32-round, write ctx [B,S,H*Dh] ----
    float inv0 = 1.f / li0, inv1 = 1.f / li1;
    const int q_lo = q0 + w * 16 + r;
    float* out_lo = g_ctx + ((size_t)batch * S_ + q_lo) * DM_ + head * DH_;
    float* out_hi = out_lo + (size_t)8 * DM_;
#pragma unroll
    for (int a = 0; a < 8; a++) {
        int d = a * 8 + 2 * c;
        *(float2*)(out_lo + d) = make_float2(tf32r(o[a][0] * inv0), tf32r(o[a][1] * inv0));
        *(float2*)(out_hi + d) = make_float2(tf32r(o[a][2] * inv1), tf32r(o[a][3] * inv1));
    }
}

// ---------------- Launch ----------------
extern "C" void kernel_launch(void* const* d_in, const int* in_sizes, int n_in,
                              void* d_out, int out_size)
{
    const float* x  = (const float*)d_in[0];
    const float* Wq = (const float*)d_in[1];
    const float* bq = (const float*)d_in[2];
    const float* Wk = (const float*)d_in[3];
    const float* bk = (const float*)d_in[4];
    const float* Wv = (const float*)d_in[5];
    const float* bv = (const float*)d_in[6];
    const float* Wc = (const float*)d_in[7];
    const float* bc = (const float*)d_in[8];
    float* out = (float*)d_out;

    float* xr; cudaGetSymbolAddress((void**)&xr, g_xr);
    float* wr; cudaGetSymbolAddress((void**)&wr, g_wr);

    static int smem_set = 0;
    if (!smem_set) {
        cudaFuncSetAttribute(attn_tc_kernel,
                             cudaFuncAttributeMaxDynamicSharedMemorySize, ATT_SMEM);
        smem_set = 1;
    }

    int nx4 = MTOT * DM_ / 4;
    int nw4 = WSZ / 4;
    round_tf32_kernel<<<(nx4 + 255) / 256, 256>>>((const float4*)x,  (float4*)xr, nx4);
    round_tf32_kernel<<<(nw4 + 255) / 256, 256>>>((const float4*)Wq, (float4*)(wr + 0 * (size_t)WSZ), nw4);
    round_tf32_kernel<<<(nw4 + 255) / 256, 256>>>((const float4*)Wk, (float4*)(wr + 1 * (size_t)WSZ), nw4);
    round_tf32_kernel<<<(nw4 + 255) / 256, 256>>>((const float4*)Wv, (float4*)(wr + 2 * (size_t)WSZ), nw4);
    round_tf32_kernel<<<(nw4 + 255) / 256, 256>>>((const float4*)Wc, (float4*)(wr + 3 * (size_t)WSZ), nw4);

    dim3 gq(MTOT / 128, DM_ / 128, 3);     // 128 x 6 x 3
    qkv_tc_kernel<<<gq, 256>>>(bq, bk, bv);

    dim3 ga(S_ / 128, H_, B_);             // 8 x 12 x 16
    attn_tc_kernel<<<ga, 256, ATT_SMEM>>>();

    dim3 gp(MTOT / 128, DM_ / 128);        // 128 x 6
    proj_tc_kernel<<<gp, 256>>>(bc, out);
}

// round 4
// speedup vs baseline: 6.7438x; 1.2369x over previous
#include <cuda_runtime.h>
#include <cstdint>

#define B_   16
#define S_   1024
#define DM_  768
#define H_   12
#define DH_  64
#define MTOT (B_ * S_)   // 16384

// Scratch (allocation-free rule: __device__ globals)
__device__ __align__(16) float g_q[(size_t)B_ * H_ * S_ * DH_];   // [b,h,s,d]
__device__ __align__(16) float g_k[(size_t)B_ * H_ * S_ * DH_];   // [b,h,s,d]
__device__ __align__(16) float g_v[(size_t)B_ * H_ * S_ * DH_];   // [b,h,d,s] (transposed!)
__device__ __align__(16) float g_ctx[(size_t)B_ * S_ * DM_];

// ---------------- helpers ----------------
__device__ __forceinline__ float tf32r(float x) {
    uint32_t u;
    asm("cvt.rna.tf32.f32 %0, %1;" : "=r"(u) : "f"(x));
    return __uint_as_float(u);
}

__device__ __forceinline__ void mma_tf32(float c[4],
                                         uint32_t a0, uint32_t a1, uint32_t a2, uint32_t a3,
                                         uint32_t b0, uint32_t b1) {
    asm volatile(
        "mma.sync.aligned.m16n8k8.row.col.f32.tf32.tf32.f32 "
        "{%0,%1,%2,%3}, {%4,%5,%6,%7}, {%8,%9}, {%0,%1,%2,%3};"
        : "+f"(c[0]), "+f"(c[1]), "+f"(c[2]), "+f"(c[3])
        : "r"(a0), "r"(a1), "r"(a2), "r"(a3), "r"(b0), "r"(b1));
}

// ---------------- tensor-core GEMM core ----------------
// Y[m,n] = sum_k A[m,k]*W[n,k]. Block 128x128, k-step 32, 256 threads.
// tf32 RN rounding fused into the smem scatter (replaces the old round kernels).
#define GBK 32
#define AF_TILES 32
#define BF_TILES 64
#define AF_STRIDE 132
#define BF_STRIDE 68
#define GEMM_SMEM_WORDS (AF_TILES * AF_STRIDE + BF_TILES * BF_STRIDE)  // 8576

__device__ __forceinline__ void tc_gemm_core(const float* __restrict__ A,
                                             const float* __restrict__ W,
                                             int m0, int n0,
                                             uint32_t* Af, uint32_t* Bf,
                                             float acc[4][4][4])
{
    const int tid  = threadIdx.x;
    const int lane = tid & 31;
    const int wid  = tid >> 5;
    const int wm   = wid >> 2;
    const int wn   = wid & 3;

    for (int kt = 0; kt < DM_; kt += GBK) {
        float4 av[4], wv[4];
#pragma unroll
        for (int i = 0; i < 4; i++) {
            int f4  = tid + (i << 8);
            int row = f4 >> 3;
            int kc  = (f4 & 7) << 2;
            av[i] = *(const float4*)(A + (size_t)(m0 + row) * DM_ + kt + kc);
            wv[i] = *(const float4*)(W + (size_t)(n0 + row) * DM_ + kt + kc);
        }
        __syncthreads();
#pragma unroll
        for (int i = 0; i < 4; i++) {
            int f4  = tid + (i << 8);
            int row = f4 >> 3;
            int kc  = (f4 & 7) << 2;
            int ks  = kc >> 3;
            int chi = (kc & 7) >> 2;
            const float* pa = (const float*)&av[i];
            const float* pw = (const float*)&wv[i];
            {
                int mt = row >> 4, rr = row & 15;
                int lb = (rr & 7) << 2;
                int rg = (rr >> 3) + (chi << 1);
                uint32_t* dst = Af + ((mt << 2) + ks) * AF_STRIDE;
#pragma unroll
                for (int j = 0; j < 4; j++)
                    dst[((lb + j) << 2) + rg] = __float_as_uint(tf32r(pa[j]));
            }
            {
                int nt = row >> 3, ln = row & 7;
                int lb = ln << 2;
                uint32_t* dst = Bf + ((nt << 2) + ks) * BF_STRIDE;
#pragma unroll
                for (int j = 0; j < 4; j++)
                    dst[((lb + j) << 1) + chi] = __float_as_uint(tf32r(pw[j]));
            }
        }
        __syncthreads();
#pragma unroll
        for (int ks = 0; ks < 4; ks++) {
            uint4 a[4]; uint2 b[4];
#pragma unroll
            for (int mi = 0; mi < 4; mi++)
                a[mi] = *(const uint4*)(Af + (((wm * 4 + mi) * 4 + ks)) * AF_STRIDE + (lane << 2));
#pragma unroll
            for (int ni = 0; ni < 4; ni++)
                b[ni] = *(const uint2*)(Bf + (((wn * 4 + ni) * 4 + ks)) * BF_STRIDE + (lane << 1));
#pragma unroll
            for (int mi = 0; mi < 4; mi++)
#pragma unroll
                for (int ni = 0; ni < 4; ni++)
                    mma_tf32(acc[mi][ni], a[mi].x, a[mi].y, a[mi].z, a[mi].w,
                             b[ni].x, b[ni].y);
        }
    }
}

// ---------------- Kernel 1: fused QKV projection ----------------
// Q,K written [b,h,s,d]; V written TRANSPOSED [b,h,d,s] via smem transpose so
// the attention kernel can cp.async V^T tiles directly. All outputs tf32-RN.
__global__ void __launch_bounds__(256) qkv_tc_kernel(
    const float* __restrict__ x,
    const float* __restrict__ Wq, const float* __restrict__ Wk,
    const float* __restrict__ Wv,
    const float* __restrict__ bq, const float* __restrict__ bk,
    const float* __restrict__ bv)
{
    __shared__ __align__(16) uint32_t SBUF[GEMM_SMEM_WORDS];
    uint32_t* Af = SBUF;
    uint32_t* Bf = SBUF + AF_TILES * AF_STRIDE;

    const int which = blockIdx.z;
    const float* W    = (which == 0) ? Wq : (which == 1) ? Wk : Wv;
    const float* bias = (which == 0) ? bq : (which == 1) ? bk : bv;

    const int m0 = blockIdx.x * 128;
    const int n0 = blockIdx.y * 128;
    float acc[4][4][4] = {};
    tc_gemm_core(x, W, m0, n0, Af, Bf, acc);

    const int tid  = threadIdx.x;
    const int lane = tid & 31;
    const int wid  = tid >> 5;
    const int wm = wid >> 2, wn = wid & 3;

    if (which < 2) {
        float* out = (which == 0) ? g_q : g_k;
#pragma unroll
        for (int mi = 0; mi < 4; mi++) {
            int r0 = m0 + wm * 64 + mi * 16 + (lane >> 2);
#pragma unroll
            for (int ni = 0; ni < 4; ni++) {
                int n  = n0 + wn * 32 + ni * 8 + ((lane & 3) << 1);
                float b0 = bias[n], b1 = bias[n + 1];
                int h = n >> 6, d = n & 63;
#pragma unroll
                for (int rr = 0; rr < 2; rr++) {
                    int m = r0 + rr * 8;
                    int bb = m >> 10, s = m & 1023;
                    float2 o = make_float2(tf32r(acc[mi][ni][rr * 2 + 0] + b0),
                                           tf32r(acc[mi][ni][rr * 2 + 1] + b1));
                    *(float2*)(out + (((size_t)(bb * H_ + h) * S_ + s) * DH_ + d)) = o;
                }
            }
        }
    } else {
        // V: transpose through smem (reuse GEMM buffer), write [b,h,d,s]
        float* T = (float*)SBUF;          // T[64][132] = 8448 words <= 8576
        const int bb = m0 >> 10, s0 = m0 & 1023;
        __syncthreads();                  // all fragment reads done
        for (int p = 0; p < 2; p++) {
            if ((wn >> 1) == p) {
#pragma unroll
                for (int mi = 0; mi < 4; mi++) {
                    int ml = wm * 64 + mi * 16 + (lane >> 2);
#pragma unroll
                    for (int ni = 0; ni < 4; ni++) {
                        int nl = (wn & 1) * 32 + ni * 8 + ((lane & 3) << 1);
                        int n  = n0 + p * 64 + nl;
                        float b0 = bias[n], b1 = bias[n + 1];
#pragma unroll
                        for (int rr = 0; rr < 2; rr++) {
                            T[nl * 132 + ml + rr * 8]       = tf32r(acc[mi][ni][rr * 2 + 0] + b0);
                            T[(nl + 1) * 132 + ml + rr * 8] = tf32r(acc[mi][ni][rr * 2 + 1] + b1);
                        }
                    }
                }
            }
            __syncthreads();
            int h = blockIdx.y * 2 + p;
            float* dst = g_v + ((size_t)(bb * H_ + h) * DH_) * S_ + s0;
            for (int i = tid; i < 64 * 32; i += 256) {
                int dr = i >> 5, c4 = (i & 31) << 2;
                *(float4*)(dst + (size_t)dr * S_ + c4) = *(const float4*)(T + dr * 132 + c4);
            }
            __syncthreads();
        }
    }
}

// ---------------- Kernel 3: output projection ----------------
__global__ void __launch_bounds__(256) proj_tc_kernel(
    const float* __restrict__ Wc, const float* __restrict__ bc,
    float* __restrict__ out)
{
    __shared__ __align__(16) uint32_t SBUF[GEMM_SMEM_WORDS];
    uint32_t* Af = SBUF;
    uint32_t* Bf = SBUF + AF_TILES * AF_STRIDE;

    const int m0 = blockIdx.x * 128;
    const int n0 = blockIdx.y * 128;
    float acc[4][4][4] = {};
    tc_gemm_core(g_ctx, Wc, m0, n0, Af, Bf, acc);

    const int lane = threadIdx.x & 31;
    const int wid  = threadIdx.x >> 5;
    const int wm = wid >> 2, wn = wid & 3;
#pragma unroll
    for (int mi = 0; mi < 4; mi++) {
        int r0 = m0 + wm * 64 + mi * 16 + (lane >> 2);
#pragma unroll
        for (int ni = 0; ni < 4; ni++) {
            int n  = n0 + wn * 32 + ni * 8 + ((lane & 3) << 1);
            float b0 = bc[n], b1 = bc[n + 1];
#pragma unroll
            for (int rr = 0; rr < 2; rr++) {
                int m = r0 + rr * 8;
                float2 o = make_float2(acc[mi][ni][rr * 2 + 0] + b0,
                                       acc[mi][ni][rr * 2 + 1] + b1);
                *(float2*)(out + (size_t)m * DM_ + n) = o;
            }
        }
    }
}

// ---------------- Kernel 2: flash attention (tf32 mma + cp.async pipeline) ----
// Block = 256 queries of one (b,h), 512 threads / 16 warps; warp owns 16 rows.
// Smem: Kbuf[2][64][68], Vtbuf[2][64][68] (double-buffered via cp.async),
// Pf = per-warp packed a-fragment P buffers (PV a-loads are LDS.128).
#define ATS  68
#define KVW  4352                       // 64*68 words
#define PFW  1056                       // 8 ks-tiles * 132 words
#define ATT_WORDS (4 * KVW + 16 * PFW)  // 34304
#define ATT_SMEM  (ATT_WORDS * 4)       // 137216 bytes

__global__ void __launch_bounds__(512) attn_tc_kernel()
{
    extern __shared__ float sm[];
    const int tid  = threadIdx.x;
    const int lane = tid & 31, w = tid >> 5;
    const int r = lane >> 2, c = lane & 3;
    const int q0   = blockIdx.x * 256;
    const int head = blockIdx.y, batch = blockIdx.z;
    const size_t base = (size_t)(batch * H_ + head) * S_ * DH_;
    const float* qb = g_q + base;
    const float* kb = g_k + base;
    const float* vb = g_v + base;      // [d][s]
    const uint32_t sb = (uint32_t)__cvta_generic_to_shared(sm);

    // ---- stage tile t into buffer buf via cp.async (K rows + V^T rows) ----
    auto stage = [&](int t, int buf) {
#pragma unroll
        for (int i = 0; i < 2; i++) {            // K: 1024 16B chunks / 512 thr
            int g = tid + (i << 9);
            int row = g >> 4, c4 = (g & 15) << 2;
            const float* src = kb + (size_t)(t * 64 + row) * DH_ + c4;
            uint32_t dst = sb + (uint32_t)(buf * KVW + row * ATS + c4) * 4u;
            asm volatile("cp.async.cg.shared.global [%0], [%1], 16;"
                         :: "r"(dst), "l"(src));
        }
#pragma unroll
        for (int i = 0; i < 2; i++) {            // V^T
            int g = tid + (i << 9);
            int row = g >> 4, c4 = (g & 15) << 2;
            const float* src = vb + (size_t)row * S_ + t * 64 + c4;
            uint32_t dst = sb + (uint32_t)((2 + buf) * KVW + row * ATS + c4) * 4u;
            asm volatile("cp.async.cg.shared.global [%0], [%1], 16;"
                         :: "r"(dst), "l"(src));
        }
        asm volatile("cp.async.commit_group;" ::: "memory");
    };

    stage(0, 0);

    // Q a-fragments in registers for the whole kernel (pre-rounded by qkv)
    uint32_t qa[8][4];
    {
        const float* qlo = qb + (size_t)(q0 + w * 16 + r) * DH_;
        const float* qhi = qlo + 8 * DH_;
#pragma unroll
        for (int ks = 0; ks < 8; ks++) {
            qa[ks][0] = __float_as_uint(qlo[ks * 8 + c]);
            qa[ks][1] = __float_as_uint(qhi[ks * 8 + c]);
            qa[ks][2] = __float_as_uint(qlo[ks * 8 + c + 4]);
            qa[ks][3] = __float_as_uint(qhi[ks * 8 + c + 4]);
        }
    }

    float o[8][4];
#pragma unroll
    for (int a = 0; a < 8; a++)
#pragma unroll
        for (int j = 0; j < 4; j++) o[a][j] = 0.f;
    float mi0 = -1e30f, mi1 = -1e30f, li0 = 0.f, li1 = 0.f;

    float* Pw = sm + 4 * KVW + w * PFW;
    const int lc    = (2 * c) & 3;            // producer scatter coords
    const int slotb = (c & 2) ? 2 : 0;

    for (int t = 0; t < S_ / 64; t++) {
        asm volatile("cp.async.wait_group 0;" ::: "memory");
        __syncthreads();                       // tile t ready; PV(t-1) done
        if (t + 1 < S_ / 64) stage(t + 1, (t + 1) & 1);

        const float* Kb = sm + (t & 1) * KVW;
        const float* Vb = sm + (2 + (t & 1)) * KVW;

        // ---- S = Q @ K^T ----
        float s[8][4];
#pragma unroll
        for (int a = 0; a < 8; a++)
#pragma unroll
            for (int j = 0; j < 4; j++) s[a][j] = 0.f;
#pragma unroll
        for (int ks = 0; ks < 8; ks++) {
#pragma unroll
            for (int a = 0; a < 8; a++) {
                const float* kp = Kb + (a * 8 + r) * ATS + ks * 8 + c;
                mma_tf32(s[a], qa[ks][0], qa[ks][1], qa[ks][2], qa[ks][3],
                         __float_as_uint(kp[0]), __float_as_uint(kp[4]));
            }
        }

        // ---- online softmax (rows r, r+8; quad-local reductions) ----
        float mx0 = -1e30f, mx1 = -1e30f;
#pragma unroll
        for (int a = 0; a < 8; a++) {
            s[a][0] *= 0.125f; s[a][1] *= 0.125f;
            s[a][2] *= 0.125f; s[a][3] *= 0.125f;
            mx0 = fmaxf(mx0, fmaxf(s[a][0], s[a][1]));
            mx1 = fmaxf(mx1, fmaxf(s[a][2], s[a][3]));
        }
        mx0 = fmaxf(mx0, __shfl_xor_sync(0xffffffffu, mx0, 1));
        mx0 = fmaxf(mx0, __shfl_xor_sync(0xffffffffu, mx0, 2));
        mx1 = fmaxf(mx1, __shfl_xor_sync(0xffffffffu, mx1, 1));
        mx1 = fmaxf(mx1, __shfl_xor_sync(0xffffffffu, mx1, 2));
        float mn0 = fmaxf(mi0, mx0), mn1 = fmaxf(mi1, mx1);
        float cr0 = __expf(mi0 - mn0), cr1 = __expf(mi1 - mn1);
        float sum0 = 0.f, sum1 = 0.f;
#pragma unroll
        for (int a = 0; a < 8; a++) {
            s[a][0] = __expf(s[a][0] - mn0);
            s[a][1] = __expf(s[a][1] - mn0);
            s[a][2] = __expf(s[a][2] - mn1);
            s[a][3] = __expf(s[a][3] - mn1);
            sum0 += s[a][0] + s[a][1];
            sum1 += s[a][2] + s[a][3];
        }
        sum0 += __shfl_xor_sync(0xffffffffu, sum0, 1);
        sum0 += __shfl_xor_sync(0xffffffffu, sum0, 2);
        sum1 += __shfl_xor_sync(0xffffffffu, sum1, 1);
        sum1 += __shfl_xor_sync(0xffffffffu, sum1, 2);
        li0 = li0 * cr0 + sum0;  mi0 = mn0;
        li1 = li1 * cr1 + sum1;  mi1 = mn1;
#pragma unroll
        for (int a = 0; a < 8; a++) {
            o[a][0] *= cr0; o[a][1] *= cr0;
            o[a][2] *= cr1; o[a][3] *= cr1;
        }

        // ---- scatter P into packed a-fragment layout (warp-local) ----
#pragma unroll
        for (int a = 0; a < 8; a++) {
            float* pe = Pw + a * 132 + ((r << 2) + lc) * 4 + slotb;
            *(float2*)(pe)     = make_float2(tf32r(s[a][0]), tf32r(s[a][2]));
            *(float2*)(pe + 4) = make_float2(tf32r(s[a][1]), tf32r(s[a][3]));
        }
        __syncwarp();

        // ---- O += P @ V (a-frags are single LDS.128) ----
#pragma unroll
        for (int ks = 0; ks < 8; ks++) {
            uint4 pa = *(const uint4*)(Pw + ks * 132 + (lane << 2));
#pragma unroll
            for (int a = 0; a < 8; a++) {
                const float* vp = Vb + (a * 8 + r) * ATS + ks * 8 + c;
                mma_tf32(o[a], pa.x, pa.y, pa.z, pa.w,
                         __float_as_uint(vp[0]), __float_as_uint(vp[4]));
            }
        }
    }

    // ---- epilogue: normalize, tf32-round, write ctx [B,S,H*Dh] ----
    float inv0 = 1.f / li0, inv1 = 1.f / li1;
    const int q_lo = q0 + w * 16 + r;
    float* out_lo = g_ctx + ((size_t)batch * S_ + q_lo) * DM_ + head * DH_;
    float* out_hi = out_lo + (size_t)8 * DM_;
#pragma unroll
    for (int a = 0; a < 8; a++) {
        int d = a * 8 + 2 * c;
        *(float2*)(out_lo + d) = make_float2(tf32r(o[a][0] * inv0), tf32r(o[a][1] * inv0));
        *(float2*)(out_hi + d) = make_float2(tf32r(o[a][2] * inv1), tf32r(o[a][3] * inv1));
    }
}

// ---------------- Launch ----------------
extern "C" void kernel_launch(void* const* d_in, const int* in_sizes, int n_in,
                              void* d_out, int out_size)
{
    const float* x  = (const float*)d_in[0];
    const float* Wq = (const float*)d_in[1];
    const float* bq = (const float*)d_in[2];
    const float* Wk = (const float*)d_in[3];
    const float* bk = (const float*)d_in[4];
    const float* Wv = (const float*)d_in[5];
    const float* bv = (const float*)d_in[6];
    const float* Wc = (const float*)d_in[7];
    const float* bc = (const float*)d_in[8];
    float* out = (float*)d_out;

    cudaFuncSetAttribute(attn_tc_kernel,
                         cudaFuncAttributeMaxDynamicSharedMemorySize, ATT_SMEM);

    dim3 gq(MTOT / 128, DM_ / 128, 3);     // 128 x 6 x 3
    qkv_tc_kernel<<<gq, 256>>>(x, Wq, Wk, Wv, bq, bk, bv);

    dim3 ga(S_ / 256, H_, B_);             // 4 x 12 x 16
    attn_tc_kernel<<<ga, 512, ATT_SMEM>>>();

    dim3 gp(MTOT / 128, DM_ / 128);        // 128 x 6
    proj_tc_kernel<<<gp, 256>>>(Wc, bc, out);
}